// round 2
// baseline (speedup 1.0000x reference)
#include <cuda_runtime.h>
#include <math.h>

// Problem: x (64, 40, 64, 500) f32  ->  per (b,f): cov 64x64, eigh, logm, triu -> (64,40,2080)
// 2560 independent 64x64 symmetric eig problems. One block per matrix,
// shared-memory parallel cyclic Jacobi with eigenvector accumulation.

#define C 64
#define TLEN 500
#define NMAT 2560          // 64*40
#define NTRI 2080          // 64*65/2
#define LDA 65             // padded stride for shared 64x64
#define NSWEEPS 8
#define THREADS 256

__global__ __launch_bounds__(THREADS, 4)
void spd_logm_kernel(const float* __restrict__ xin, float* __restrict__ out)
{
    __shared__ float sA[C * LDA];       // covariance -> diagonalized -> W
    __shared__ float sV[C * LDA];       // eigenvectors (aliased as x-tile during cov phase)
    __shared__ float sc[32], ssn[32];
    __shared__ int   spp[32], sqq[32];
    __shared__ float ssum[C];
    __shared__ float slam[C];

    const int tid = threadIdx.x;
    const int mat = blockIdx.x;
    const float* __restrict__ xm = xin + (size_t)mat * (C * TLEN);
    float* __restrict__ om = out + (size_t)mat * NTRI;

    // ---------------- Phase 1: covariance (one pass over gmem) ----------------
    // Gram accumulation with 4x4 register blocking on a 16x16 thread grid,
    // streaming 64x32 time-tiles through shared (aliased onto sV, stride 33).
    {
        float* xt = sV;                 // 64 x 32 tile, stride 33 (2112 floats < 4160)
        const int ty = tid >> 4;        // 0..15 -> rows 4*ty..4*ty+3
        const int tx = tid & 15;        // 0..15 -> cols 4*tx..4*tx+3
        float acc[4][4];
#pragma unroll
        for (int i = 0; i < 4; i++)
#pragma unroll
            for (int j = 0; j < 4; j++) acc[i][j] = 0.0f;
        float rowsum = 0.0f;            // valid for tid < 64

        for (int t0 = 0; t0 < TLEN; t0 += 32) {
            // load tile: 2048 elements, 8 per thread, coalesced along t
#pragma unroll
            for (int it = 0; it < 8; it++) {
                int e = tid + it * THREADS;
                int r = e >> 5, cc = e & 31;
                int t = t0 + cc;
                xt[r * 33 + cc] = (t < TLEN) ? xm[r * TLEN + t] : 0.0f;
            }
            __syncthreads();
            if (tid < C) {
#pragma unroll
                for (int cc = 0; cc < 32; cc++) rowsum += xt[tid * 33 + cc];
            }
#pragma unroll 4
            for (int tt = 0; tt < 32; tt++) {
                float a0 = xt[(4 * ty + 0) * 33 + tt];
                float a1 = xt[(4 * ty + 1) * 33 + tt];
                float a2 = xt[(4 * ty + 2) * 33 + tt];
                float a3 = xt[(4 * ty + 3) * 33 + tt];
                float b0 = xt[(4 * tx + 0) * 33 + tt];
                float b1 = xt[(4 * tx + 1) * 33 + tt];
                float b2 = xt[(4 * tx + 2) * 33 + tt];
                float b3 = xt[(4 * tx + 3) * 33 + tt];
                acc[0][0] += a0 * b0; acc[0][1] += a0 * b1; acc[0][2] += a0 * b2; acc[0][3] += a0 * b3;
                acc[1][0] += a1 * b0; acc[1][1] += a1 * b1; acc[1][2] += a1 * b2; acc[1][3] += a1 * b3;
                acc[2][0] += a2 * b0; acc[2][1] += a2 * b1; acc[2][2] += a2 * b2; acc[2][3] += a2 * b3;
                acc[3][0] += a3 * b0; acc[3][1] += a3 * b1; acc[3][2] += a3 * b2; acc[3][3] += a3 * b3;
            }
            __syncthreads();
        }
        if (tid < C) ssum[tid] = rowsum;
        __syncthreads();

        const float invT  = 1.0f / (float)TLEN;
        const float invT1 = 1.0f / (float)(TLEN - 1);
#pragma unroll
        for (int i = 0; i < 4; i++) {
            float si = ssum[4 * ty + i];
#pragma unroll
            for (int j = 0; j < 4; j++) {
                float sj = ssum[4 * tx + j];
                sA[(4 * ty + i) * LDA + (4 * tx + j)] =
                    (acc[i][j] - si * sj * invT) * invT1;
            }
        }
    }
    __syncthreads();

    // V = I
#pragma unroll
    for (int it = 0; it < 16; it++) {
        int e = tid + it * THREADS;
        int i = e >> 6, j = e & 63;
        sV[i * LDA + j] = (i == j) ? 1.0f : 0.0f;
    }

    // ---------------- Phase 2: parallel cyclic Jacobi ----------------
    for (int sweep = 0; sweep < NSWEEPS; sweep++) {
        for (int r = 0; r < 63; r++) {
            __syncthreads();
            if (tid < 32) {
                int p, q;
                if (tid == 0) { p = 63; q = r % 63; }
                else {
                    p = (r + tid) % 63;
                    q = (r - tid + 63) % 63;
                }
                float app = sA[p * LDA + p];
                float aqq = sA[q * LDA + q];
                float apq = sA[p * LDA + q];
                float cc, ss;
                if (fabsf(apq) > 1e-36f) {
                    float theta = (aqq - app) / (2.0f * apq);
                    float t = copysignf(1.0f, theta) /
                              (fabsf(theta) + sqrtf(theta * theta + 1.0f));
                    cc = rsqrtf(t * t + 1.0f);
                    ss = t * cc;
                } else { cc = 1.0f; ss = 0.0f; }
                sc[tid] = cc; ssn[tid] = ss; spp[tid] = p; sqq[tid] = q;
            }
            __syncthreads();
            // row phase: A <- J^T A   (32 pairs x 64 cols)
#pragma unroll
            for (int it = 0; it < 8; it++) {
                int e = tid + it * THREADS;
                int k = e >> 6, j = e & 63;
                int p = spp[k], q = sqq[k];
                float cc = sc[k], ss = ssn[k];
                float ap = sA[p * LDA + j], aq = sA[q * LDA + j];
                sA[p * LDA + j] = cc * ap - ss * aq;
                sA[q * LDA + j] = ss * ap + cc * aq;
            }
            __syncthreads();
            // col phase: A <- A J ; V <- V J   (32 pairs x 64 rows)
#pragma unroll
            for (int it = 0; it < 8; it++) {
                int e = tid + it * THREADS;
                int k = e >> 6, i = e & 63;
                int p = spp[k], q = sqq[k];
                float cc = sc[k], ss = ssn[k];
                float ap = sA[i * LDA + p], aq = sA[i * LDA + q];
                sA[i * LDA + p] = cc * ap - ss * aq;
                sA[i * LDA + q] = ss * ap + cc * aq;
                float vp = sV[i * LDA + p], vq = sV[i * LDA + q];
                sV[i * LDA + p] = cc * vp - ss * vq;
                sV[i * LDA + q] = ss * vp + cc * vq;
            }
        }
    }
    __syncthreads();

    // ---------------- Phase 3: log-eigenvalues + reconstruction ----------------
    if (tid < C) {
        float lam = sA[tid * LDA + tid];
        lam = fmaxf(lam, 1e-10f);
        slam[tid] = logf(lam);
    }
    __syncthreads();
    // W = V * diag(log lam), overwrite sA
#pragma unroll
    for (int it = 0; it < 16; it++) {
        int e = tid + it * THREADS;
        int i = e >> 6, j = e & 63;
        sA[i * LDA + j] = sV[i * LDA + j] * slam[j];
    }
    __syncthreads();

    // logm[i][j] = sum_e W[i][e] * V[j][e], upper triangle only
#pragma unroll
    for (int it = 0; it < 16; it++) {
        int e2 = tid + it * THREADS;
        int i = e2 >> 6, j = e2 & 63;
        if (i <= j) {
            const float* wi = &sA[i * LDA];
            const float* vj = &sV[j * LDA];
            float dot = 0.0f;
#pragma unroll
            for (int e = 0; e < C; e++) dot += wi[e] * vj[e];
            int o = i * C - ((i * (i - 1)) >> 1) + (j - i);
            om[o] = dot;
        }
    }
}

extern "C" void kernel_launch(void* const* d_in, const int* in_sizes, int n_in,
                              void* d_out, int out_size)
{
    const float* x = (const float*)d_in[0];
    float* out = (float*)d_out;
    spd_logm_kernel<<<NMAT, THREADS>>>(x, out);
}

// round 3
// speedup vs baseline: 1.2740x; 1.2740x over previous
#include <cuda_runtime.h>
#include <math.h>

// x (64, 40, 64, 500) f32 -> per (b,f): cov 64x64, eigh (parallel Jacobi), logm, triu -> (64,40,2080)
// One block per matrix. Fused two-sided Jacobi update: A' = J^T A J decomposes into
// independent 2x2 blocks over the pair partition -> single read-4/write-4 pass.

#define C 64
#define TLEN 500
#define NMAT 2560
#define NTRI 2080
#define LDA 65
#define NSWEEPS 7
#define THREADS 256

__global__ __launch_bounds__(THREADS, 4)
void spd_logm_kernel(const float* __restrict__ xin, float* __restrict__ out)
{
    __shared__ float sA[C * LDA];
    __shared__ float sV[C * LDA];
    __shared__ float sc[32], ssn[32];
    __shared__ int   spp[32], sqq[32];
    __shared__ float ssum[C];
    __shared__ float slam[C];

    const int tid = threadIdx.x;
    const int mat = blockIdx.x;
    const float* __restrict__ xm = xin + (size_t)mat * (C * TLEN);
    float* __restrict__ om = out + (size_t)mat * NTRI;

    // ---------------- Phase 1: covariance ----------------
    {
        float* xt = sV;                 // 64 x 32 tile, stride 33
        const int ty = tid >> 4;
        const int tx = tid & 15;
        float acc[4][4];
#pragma unroll
        for (int i = 0; i < 4; i++)
#pragma unroll
            for (int j = 0; j < 4; j++) acc[i][j] = 0.0f;
        float rowsum = 0.0f;

        for (int t0 = 0; t0 < TLEN; t0 += 32) {
#pragma unroll
            for (int it = 0; it < 8; it++) {
                int e = tid + it * THREADS;
                int r = e >> 5, cc = e & 31;
                int t = t0 + cc;
                xt[r * 33 + cc] = (t < TLEN) ? xm[r * TLEN + t] : 0.0f;
            }
            __syncthreads();
            if (tid < C) {
#pragma unroll
                for (int cc = 0; cc < 32; cc++) rowsum += xt[tid * 33 + cc];
            }
#pragma unroll 4
            for (int tt = 0; tt < 32; tt++) {
                float a0 = xt[(4 * ty + 0) * 33 + tt];
                float a1 = xt[(4 * ty + 1) * 33 + tt];
                float a2 = xt[(4 * ty + 2) * 33 + tt];
                float a3 = xt[(4 * ty + 3) * 33 + tt];
                float b0 = xt[(4 * tx + 0) * 33 + tt];
                float b1 = xt[(4 * tx + 1) * 33 + tt];
                float b2 = xt[(4 * tx + 2) * 33 + tt];
                float b3 = xt[(4 * tx + 3) * 33 + tt];
                acc[0][0] += a0 * b0; acc[0][1] += a0 * b1; acc[0][2] += a0 * b2; acc[0][3] += a0 * b3;
                acc[1][0] += a1 * b0; acc[1][1] += a1 * b1; acc[1][2] += a1 * b2; acc[1][3] += a1 * b3;
                acc[2][0] += a2 * b0; acc[2][1] += a2 * b1; acc[2][2] += a2 * b2; acc[2][3] += a2 * b3;
                acc[3][0] += a3 * b0; acc[3][1] += a3 * b1; acc[3][2] += a3 * b2; acc[3][3] += a3 * b3;
            }
            __syncthreads();
        }
        if (tid < C) ssum[tid] = rowsum;
        __syncthreads();

        const float invT  = 1.0f / (float)TLEN;
        const float invT1 = 1.0f / (float)(TLEN - 1);
#pragma unroll
        for (int i = 0; i < 4; i++) {
            float si = ssum[4 * ty + i];
#pragma unroll
            for (int j = 0; j < 4; j++) {
                float sj = ssum[4 * tx + j];
                sA[(4 * ty + i) * LDA + (4 * tx + j)] =
                    (acc[i][j] - si * sj * invT) * invT1;
            }
        }
    }
    __syncthreads();

    // V = I
#pragma unroll
    for (int it = 0; it < 16; it++) {
        int e = tid + it * THREADS;
        int i = e >> 6, j = e & 63;
        sV[i * LDA + j] = (i == j) ? 1.0f : 0.0f;
    }
    __syncthreads();

    // ---------------- Phase 2: parallel cyclic Jacobi (fused two-sided) ----------------
    for (int sweep = 0; sweep < NSWEEPS; sweep++) {
        for (int r = 0; r < 63; r++) {
            if (tid < 32) {
                int p, q;
                if (tid == 0) { p = 63; q = r % 63; }
                else {
                    p = (r + tid) % 63;
                    q = (r - tid + 63) % 63;
                }
                float app = sA[p * LDA + p];
                float aqq = sA[q * LDA + q];
                float apq = sA[p * LDA + q];
                float cc, ss;
                if (fabsf(apq) > 1e-36f) {
                    float theta = (aqq - app) / (2.0f * apq);
                    float t = copysignf(1.0f, theta) /
                              (fabsf(theta) + sqrtf(theta * theta + 1.0f));
                    cc = rsqrtf(t * t + 1.0f);
                    ss = t * cc;
                } else { cc = 1.0f; ss = 0.0f; }
                sc[tid] = cc; ssn[tid] = ss; spp[tid] = p; sqq[tid] = q;
            }
            __syncthreads();

            // Fused A' = J^T A J : 32x32 blocks of 2x2, each exclusively owned.
#pragma unroll
            for (int it = 0; it < 4; it++) {
                int e = tid + it * THREADS;       // 0..1023
                int k1 = e >> 5, k2 = e & 31;
                int p1 = spp[k1], q1 = sqq[k1];
                int p2 = spp[k2], q2 = sqq[k2];
                float c1 = sc[k1], s1 = ssn[k1];
                float c2 = sc[k2], s2 = ssn[k2];
                float a00 = sA[p1 * LDA + p2], a01 = sA[p1 * LDA + q2];
                float a10 = sA[q1 * LDA + p2], a11 = sA[q1 * LDA + q2];
                float t00 = c1 * a00 - s1 * a10, t01 = c1 * a01 - s1 * a11;
                float t10 = s1 * a00 + c1 * a10, t11 = s1 * a01 + c1 * a11;
                sA[p1 * LDA + p2] = c2 * t00 - s2 * t01;
                sA[p1 * LDA + q2] = s2 * t00 + c2 * t01;
                sA[q1 * LDA + p2] = c2 * t10 - s2 * t11;
                sA[q1 * LDA + q2] = s2 * t10 + c2 * t11;
            }
            // V <- V J : 32 pairs x 64 rows
#pragma unroll
            for (int it = 0; it < 8; it++) {
                int e = tid + it * THREADS;
                int k = e >> 6, i = e & 63;
                int p = spp[k], q = sqq[k];
                float cc = sc[k], ss = ssn[k];
                float vp = sV[i * LDA + p], vq = sV[i * LDA + q];
                sV[i * LDA + p] = cc * vp - ss * vq;
                sV[i * LDA + q] = ss * vp + cc * vq;
            }
            __syncthreads();
        }
    }

    // ---------------- Phase 3: log-eigenvalues + reconstruction ----------------
    if (tid < C) {
        float lam = sA[tid * LDA + tid];
        lam = fmaxf(lam, 1e-10f);
        slam[tid] = logf(lam);
    }
    __syncthreads();
#pragma unroll
    for (int it = 0; it < 16; it++) {
        int e = tid + it * THREADS;
        int i = e >> 6, j = e & 63;
        sA[i * LDA + j] = sV[i * LDA + j] * slam[j];
    }
    __syncthreads();

#pragma unroll
    for (int it = 0; it < 16; it++) {
        int e2 = tid + it * THREADS;
        int i = e2 >> 6, j = e2 & 63;
        if (i <= j) {
            const float* wi = &sA[i * LDA];
            const float* vj = &sV[j * LDA];
            float dot = 0.0f;
#pragma unroll
            for (int e = 0; e < C; e++) dot += wi[e] * vj[e];
            int o = i * C - ((i * (i - 1)) >> 1) + (j - i);
            om[o] = dot;
        }
    }
}

extern "C" void kernel_launch(void* const* d_in, const int* in_sizes, int n_in,
                              void* d_out, int out_size)
{
    const float* x = (const float*)d_in[0];
    float* out = (float*)d_out;
    spd_logm_kernel<<<NMAT, THREADS>>>(x, out);
}

// round 4
// speedup vs baseline: 2.0959x; 1.6452x over previous
#include <cuda_runtime.h>
#include <math.h>

// x (64, 40, 64, 500) f32 -> per (b,f): cov 64x64, eigh (parallel Jacobi), logm, triu -> (64,40,2080)
// One block per matrix. Fused two-sided Jacobi A-update (independent 2x2 blocks),
// transposed eigenvector matrix Vt with float2-vectorized pair-row updates,
// packed rotation parameters (float2 c/s, packed p|q<<8).

#define C 64
#define TLEN 500
#define NMAT 2560
#define NTRI 2080
#define LDA 65          // stride for sA
#define LDV 66          // stride for sVt (even -> float2-aligned rows)
#define NSWEEPS 6
#define THREADS 256

__global__ __launch_bounds__(THREADS, 4)
void spd_logm_kernel(const float* __restrict__ xin, float* __restrict__ out)
{
    __shared__ float  sA[C * LDA];        // covariance -> diagonalized -> W
    __shared__ float  sVt[C * LDV];       // eigenvectors TRANSPOSED (row j = eigvec j)
    __shared__ float2 scs[32];            // (c, s) per pair
    __shared__ int    spq[32];            // p | (q<<8)
    __shared__ float  ssum[C];
    __shared__ float  slam[C];

    const int tid = threadIdx.x;
    const int mat = blockIdx.x;
    const float* __restrict__ xm = xin + (size_t)mat * (C * TLEN);
    float* __restrict__ om = out + (size_t)mat * NTRI;

    // ---------------- Phase 1: covariance ----------------
    {
        float* xt = sVt;                // 64 x 32 tile, stride 33 (2112 <= 4224 floats)
        const int ty = tid >> 4;
        const int tx = tid & 15;
        float acc[4][4];
#pragma unroll
        for (int i = 0; i < 4; i++)
#pragma unroll
            for (int j = 0; j < 4; j++) acc[i][j] = 0.0f;
        float rowsum = 0.0f;

        for (int t0 = 0; t0 < TLEN; t0 += 32) {
#pragma unroll
            for (int it = 0; it < 8; it++) {
                int e = tid + it * THREADS;
                int r = e >> 5, cc = e & 31;
                int t = t0 + cc;
                xt[r * 33 + cc] = (t < TLEN) ? xm[r * TLEN + t] : 0.0f;
            }
            __syncthreads();
            if (tid < C) {
#pragma unroll
                for (int cc = 0; cc < 32; cc++) rowsum += xt[tid * 33 + cc];
            }
#pragma unroll 4
            for (int tt = 0; tt < 32; tt++) {
                float a0 = xt[(4 * ty + 0) * 33 + tt];
                float a1 = xt[(4 * ty + 1) * 33 + tt];
                float a2 = xt[(4 * ty + 2) * 33 + tt];
                float a3 = xt[(4 * ty + 3) * 33 + tt];
                float b0 = xt[(4 * tx + 0) * 33 + tt];
                float b1 = xt[(4 * tx + 1) * 33 + tt];
                float b2 = xt[(4 * tx + 2) * 33 + tt];
                float b3 = xt[(4 * tx + 3) * 33 + tt];
                acc[0][0] += a0 * b0; acc[0][1] += a0 * b1; acc[0][2] += a0 * b2; acc[0][3] += a0 * b3;
                acc[1][0] += a1 * b0; acc[1][1] += a1 * b1; acc[1][2] += a1 * b2; acc[1][3] += a1 * b3;
                acc[2][0] += a2 * b0; acc[2][1] += a2 * b1; acc[2][2] += a2 * b2; acc[2][3] += a2 * b3;
                acc[3][0] += a3 * b0; acc[3][1] += a3 * b1; acc[3][2] += a3 * b2; acc[3][3] += a3 * b3;
            }
            __syncthreads();
        }
        if (tid < C) ssum[tid] = rowsum;
        __syncthreads();

        const float invT  = 1.0f / (float)TLEN;
        const float invT1 = 1.0f / (float)(TLEN - 1);
#pragma unroll
        for (int i = 0; i < 4; i++) {
            float si = ssum[4 * ty + i];
#pragma unroll
            for (int j = 0; j < 4; j++) {
                float sj = ssum[4 * tx + j];
                sA[(4 * ty + i) * LDA + (4 * tx + j)] =
                    (acc[i][j] - si * sj * invT) * invT1;
            }
        }
    }
    __syncthreads();

    // Vt = I
#pragma unroll
    for (int it = 0; it < 16; it++) {
        int e = tid + it * THREADS;
        int i = e >> 6, j = e & 63;
        sVt[i * LDV + j] = (i == j) ? 1.0f : 0.0f;
    }
    __syncthreads();

    // ---------------- Phase 2: parallel cyclic Jacobi ----------------
    for (int sweep = 0; sweep < NSWEEPS; sweep++) {
        for (int r = 0; r < 63; r++) {
            if (tid < 32) {
                int p, q;
                if (tid == 0) { p = 63; q = r % 63; }
                else {
                    p = (r + tid) % 63;
                    q = (r - tid + 63) % 63;
                }
                float app = sA[p * LDA + p];
                float aqq = sA[q * LDA + q];
                float apq = sA[p * LDA + q];
                float cc, ss;
                if (fabsf(apq) > 1e-36f) {
                    float theta = (aqq - app) / (2.0f * apq);
                    float t = copysignf(1.0f, theta) /
                              (fabsf(theta) + sqrtf(theta * theta + 1.0f));
                    cc = rsqrtf(t * t + 1.0f);
                    ss = t * cc;
                } else { cc = 1.0f; ss = 0.0f; }
                scs[tid] = make_float2(cc, ss);
                spq[tid] = p | (q << 8);
            }
            __syncthreads();

            // Fused A' = J^T A J : 32x32 blocks of 2x2, each exclusively owned.
#pragma unroll
            for (int it = 0; it < 4; it++) {
                int e = tid + it * THREADS;       // 0..1023
                int k1 = e >> 5, k2 = e & 31;
                int pq1 = spq[k1], pq2 = spq[k2];
                float2 cs1 = scs[k1], cs2 = scs[k2];
                int p1 = pq1 & 255, q1 = pq1 >> 8;
                int p2 = pq2 & 255, q2 = pq2 >> 8;
                float a00 = sA[p1 * LDA + p2], a01 = sA[p1 * LDA + q2];
                float a10 = sA[q1 * LDA + p2], a11 = sA[q1 * LDA + q2];
                float t00 = cs1.x * a00 - cs1.y * a10, t01 = cs1.x * a01 - cs1.y * a11;
                float t10 = cs1.y * a00 + cs1.x * a10, t11 = cs1.y * a01 + cs1.x * a11;
                sA[p1 * LDA + p2] = cs2.x * t00 - cs2.y * t01;
                sA[p1 * LDA + q2] = cs2.y * t00 + cs2.x * t01;
                sA[q1 * LDA + p2] = cs2.x * t10 - cs2.y * t11;
                sA[q1 * LDA + q2] = cs2.y * t10 + cs2.x * t11;
            }
            // Vt rows p,q: float2-vectorized (1024 work items, 2 floats each)
#pragma unroll
            for (int it = 0; it < 4; it++) {
                int e = tid + it * THREADS;       // 0..1023
                int k = e >> 5, i2 = e & 31;      // i2 = float2 index along row
                int pq = spq[k];
                float2 cs = scs[k];
                int p = pq & 255, q = pq >> 8;
                float2* vp2 = (float2*)&sVt[p * LDV];
                float2* vq2 = (float2*)&sVt[q * LDV];
                float2 vp = vp2[i2], vq = vq2[i2];
                float2 np, nq;
                np.x = cs.x * vp.x - cs.y * vq.x;
                np.y = cs.x * vp.y - cs.y * vq.y;
                nq.x = cs.y * vp.x + cs.x * vq.x;
                nq.y = cs.y * vp.y + cs.x * vq.y;
                vp2[i2] = np;
                vq2[i2] = nq;
            }
            __syncthreads();
        }
    }

    // ---------------- Phase 3: log-eigenvalues + reconstruction ----------------
    if (tid < C) {
        float lam = sA[tid * LDA + tid];
        lam = fmaxf(lam, 1e-10f);
        slam[tid] = logf(lam);
    }
    __syncthreads();
    // W[e][i] = Vt[e][i] * log(lam[e]), stored into sA rows (stride LDA)
#pragma unroll
    for (int it = 0; it < 16; it++) {
        int e2 = tid + it * THREADS;
        int e = e2 >> 6, i = e2 & 63;
        sA[e * LDA + i] = sVt[e * LDV + i] * slam[e];
    }
    __syncthreads();

    // logm[i][j] = sum_e W[e][i] * Vt[e][j], upper triangle only
#pragma unroll
    for (int it = 0; it < 16; it++) {
        int e2 = tid + it * THREADS;
        int i = e2 >> 6, j = e2 & 63;
        if (i <= j) {
            float dot = 0.0f;
#pragma unroll
            for (int e = 0; e < C; e++)
                dot += sA[e * LDA + i] * sVt[e * LDV + j];
            int o = i * C - ((i * (i - 1)) >> 1) + (j - i);
            om[o] = dot;
        }
    }
}

extern "C" void kernel_launch(void* const* d_in, const int* in_sizes, int n_in,
                              void* d_out, int out_size)
{
    const float* x = (const float*)d_in[0];
    float* out = (float*)d_out;
    spd_logm_kernel<<<NMAT, THREADS>>>(x, out);
}